// round 15
// baseline (speedup 1.0000x reference)
#include <cuda_runtime.h>
#include <cuda_fp16.h>

#define NN 100000
#define EE 1600000
#define DD 128
#define GB_GEMM 1563      // ceil(NN/64) gemm blocks (also BN-stat partials)
#define SCAN_NB 98        // ceil(NN / 1024)

// ---------------- scratch (device globals: no allocation allowed) ----------------
__device__ __align__(16) float g_deg[NN];            // dinv (float)
__device__ __align__(16) int   g_cnt[NN];            // int degree
__device__ __align__(16) int   g_offp[NN];           // per-block exclusive scan
__device__ __align__(16) int   g_off[NN + 1];        // CSR offsets
__device__ __align__(16) int   g_cur[NN];            // scatter cursors
__device__ __align__(16) int   g_bsum[128];          // scan block sums
__device__ __align__(16) int   g_bpre[128];          // scan block prefixes
__device__ __align__(16) int2  g_edge[EE];           // CSR: {row*32, val bits}
__device__ __align__(16) __half g_h[NN * DD];        // current activations (fp16)
__device__ __align__(16) __half g_x0[NN * DD];       // first embedding (fp16)
__device__ __align__(16) float g_tmp[NN * DD];       // GEMM output (pre-BN)
__device__ __align__(16) float g_agg[NN * DD];       // SPMM output (fp32)
__device__ __align__(16) float g_part[GB_GEMM * 256]; // per gemm-block [sum(128)|sumsq(128)]
__device__ __align__(16) float g_scale[DD];
__device__ __align__(16) float g_shift[DD];

// ---- packed fp32x2 helpers (SASS FFMA2 path, exact fp32 math) ----
#define FMA_F32X2(d, a, b, c) \
    asm("fma.rn.f32x2 %0, %1, %2, %3;" : "=l"(d) : "l"(a), "l"(b), "l"(c))
#define PACK_RR(out, f) \
    asm("mov.b64 %0, {%1, %1};" : "=l"(out) : "r"(__float_as_uint(f)))
#define UNPACK2(lo, hi, in) \
    asm("mov.b64 {%0, %1}, %2;" : "=r"(lo), "=r"(hi) : "l"(in))

// ---------------- degree ----------------
__global__ void zero_cnt_kernel() {
    int i = blockIdx.x * blockDim.x + threadIdx.x;
    if (i < NN) g_cnt[i] = 0;
}

__global__ void compute_cnt_kernel(const int* __restrict__ col) {
    int e = blockIdx.x * blockDim.x + threadIdx.x;   // EE % 256 == 0
    atomicAdd(&g_cnt[col[e]], 1);
}

__global__ void dinv_kernel() {
    int i = blockIdx.x * blockDim.x + threadIdx.x;
    if (i < NN) {
        int d = g_cnt[i];
        g_deg[i] = d > 0 ? rsqrtf((float)d) : 0.f;
    }
}

// ---------------- prefix scan (3 phases) ----------------
__global__ void __launch_bounds__(1024) scan1_kernel() {
    __shared__ int sh[1024];
    int i = blockIdx.x * 1024 + threadIdx.x;
    int v = (i < NN) ? g_cnt[i] : 0;
    sh[threadIdx.x] = v;
    __syncthreads();
#pragma unroll
    for (int off = 1; off < 1024; off <<= 1) {
        int t = 0;
        if (threadIdx.x >= off) t = sh[threadIdx.x - off];
        __syncthreads();
        sh[threadIdx.x] += t;
        __syncthreads();
    }
    if (i < NN) g_offp[i] = sh[threadIdx.x] - v;     // exclusive within block
    if (threadIdx.x == 1023) g_bsum[blockIdx.x] = sh[1023];
}

__global__ void scan2_kernel() {                     // 1 block, 128 threads
    __shared__ int sh[128];
    int t = threadIdx.x;
    int v = (t < SCAN_NB) ? g_bsum[t] : 0;
    sh[t] = v;
    __syncthreads();
#pragma unroll
    for (int off = 1; off < 128; off <<= 1) {
        int u = 0;
        if (t >= off) u = sh[t - off];
        __syncthreads();
        sh[t] += u;
        __syncthreads();
    }
    if (t < SCAN_NB) g_bpre[t] = sh[t] - v;          // exclusive
}

__global__ void scan3_kernel() {
    int i = blockIdx.x * blockDim.x + threadIdx.x;
    if (i < NN) {
        g_off[i] = g_offp[i] + g_bpre[i >> 10];
        g_cur[i] = 0;
    }
    if (i == 0) g_off[NN] = EE;
}

// ---------------- CSR scatter (sort edges by col) + weight ----------------
__global__ void scatter_kernel(const int* __restrict__ row, const int* __restrict__ col) {
    int e = blockIdx.x * blockDim.x + threadIdx.x;   // EE % 256 == 0
    int r = row[e];
    int c = col[e];
    int p = g_off[c] + atomicAdd(&g_cur[c], 1);
    int2 ev;
    ev.x = r * 32;                                   // pre-scaled uint2 row base
    ev.y = __float_as_int(g_deg[c] * g_deg[r]);
    g_edge[p] = ev;
}

// ---------------- SPMM (gather, no atomics): one warp per destination node ----------------
__global__ void __launch_bounds__(256) spmm_csr_kernel() {
    int n = blockIdx.x * 8 + (threadIdx.x >> 5);     // NN % 8 == 0
    int lane = threadIdx.x & 31;
    int s = g_off[n];
    int e = g_off[n + 1];
    float4 acc = make_float4(0.f, 0.f, 0.f, 0.f);
#pragma unroll 4
    for (int p = s; p < e; p++) {
        int2 ev = __ldg(g_edge + p);                 // warp-uniform broadcast
        float v = __int_as_float(ev.y);
        uint2 hv = ((const uint2*)g_h)[ev.x + lane]; // 4 halves (8 B) gather
        float2 f01 = __half22float2(*(const __half2*)&hv.x);
        float2 f23 = __half22float2(*(const __half2*)&hv.y);
        acc.x += v * f01.x; acc.y += v * f01.y;
        acc.z += v * f23.x; acc.w += v * f23.y;
    }
    ((float4*)g_agg)[n * 32 + lane] = acc;
}

// ---------------- 128-wide SGEMM + fused BN stats ----------------
// g_tmp = A @ W^T + bias ; g_part[blk] = per-column {sum, sumsq} of this tile.
// W staged in shared as adjacent col-pairs (c, c+32) -> LDS.64, FFMA2 inner loop.
__global__ void __launch_bounds__(256) gemm128_kernel(const float* __restrict__ Aext,
                                                      int useAgg,
                                                      const float* __restrict__ W,
                                                      const float* __restrict__ bias) {
    extern __shared__ float sh[];
    float*  xs  = sh;                          // 64*128 floats (32 KB)
    float2* ws2 = (float2*)(sh + 64 * 128);    // 128 k x 64 pairs (64 KB)
    const float* A = useAgg ? g_agg : Aext;
    int tid = threadIdx.x;
    int rowBase = blockIdx.x * 64;

    // stage W as pairs: ws2[k*64 + p] = { W[c0][k], W[c1][k] }
    //   p in [0,32):  c0 = p,      c1 = p+32
    //   p in [32,64): c0 = p+32,   c1 = p+64
#pragma unroll
    for (int i = 0; i < 32; i++) {             // 8192 float2
        int idx = i * 256 + tid;
        int k = idx >> 6, p = idx & 63;
        int c0 = (p < 32) ? p : p + 32;
        int c1 = c0 + 32;
        ws2[k * 64 + p] = make_float2(W[c0 * DD + k], W[c1 * DD + k]);
    }
#pragma unroll
    for (int i = 0; i < 32; i++) {             // stage A tile
        int idx = i * 256 + tid;
        int r = rowBase + (idx >> 7);
        xs[idx] = (r < NN) ? A[r * DD + (idx & 127)] : 0.f;
    }
    __syncthreads();

    int tx = tid & 31;        // cols tx, tx+32 (pair0) and tx+64, tx+96 (pair1)
    int ty = tid >> 5;        // rows ty*8 .. ty*8+7
    unsigned long long acc0[8], acc1[8];
#pragma unroll
    for (int j = 0; j < 8; j++) { acc0[j] = 0ULL; acc1[j] = 0ULL; }

    const float4* xs4 = (const float4*)xs + ty * 8 * 32;
    for (int k4 = 0; k4 < 32; k4++) {
        unsigned long long w0[4], w1[4];
#pragma unroll
        for (int kk = 0; kk < 4; kk++) {
            float2 a = ws2[(k4 * 4 + kk) * 64 + tx];
            float2 b = ws2[(k4 * 4 + kk) * 64 + 32 + tx];
            w0[kk] = *(unsigned long long*)&a;
            w1[kk] = *(unsigned long long*)&b;
        }
#pragma unroll
        for (int j = 0; j < 8; j++) {
            float4 xv = xs4[j * 32 + k4];
            unsigned long long xx;
            PACK_RR(xx, xv.x);
            FMA_F32X2(acc0[j], xx, w0[0], acc0[j]);
            FMA_F32X2(acc1[j], xx, w1[0], acc1[j]);
            PACK_RR(xx, xv.y);
            FMA_F32X2(acc0[j], xx, w0[1], acc0[j]);
            FMA_F32X2(acc1[j], xx, w1[1], acc1[j]);
            PACK_RR(xx, xv.z);
            FMA_F32X2(acc0[j], xx, w0[2], acc0[j]);
            FMA_F32X2(acc1[j], xx, w1[2], acc1[j]);
            PACK_RR(xx, xv.w);
            FMA_F32X2(acc0[j], xx, w0[3], acc0[j]);
            FMA_F32X2(acc1[j], xx, w1[3], acc1[j]);
        }
    }

    float b0 = __ldg(bias + tx), b1 = __ldg(bias + tx + 32);
    float b2 = __ldg(bias + tx + 64), b3 = __ldg(bias + tx + 96);
    float s0 = 0.f, s1 = 0.f, s2c = 0.f, s3 = 0.f;       // col sums
    float q0 = 0.f, q1 = 0.f, q2 = 0.f, q3 = 0.f;        // col sumsq
#pragma unroll
    for (int j = 0; j < 8; j++) {
        int r = rowBase + ty * 8 + j;
        if (r < NN) {
            unsigned u0, u1;
            UNPACK2(u0, u1, acc0[j]);
            float v0 = __uint_as_float(u0) + b0;
            float v1 = __uint_as_float(u1) + b1;
            UNPACK2(u0, u1, acc1[j]);
            float v2 = __uint_as_float(u0) + b2;
            float v3 = __uint_as_float(u1) + b3;
            float* o = g_tmp + r * DD + tx;
            o[0] = v0; o[32] = v1; o[64] = v2; o[96] = v3;
            s0 += v0; s1 += v1; s2c += v2; s3 += v3;
            q0 += v0 * v0; q1 += v1 * v1; q2 += v2 * v2; q3 += v3 * v3;
        }
    }

    // reduce stats over the 8 row-groups (reuse xs; padded stride 9)
    __syncthreads();
    float* sred = sh;     // [stat][c][ty] : stat*1152 + c*9 + ty
    sred[(tx)      * 9 + ty]        = s0;
    sred[(tx + 32) * 9 + ty]        = s1;
    sred[(tx + 64) * 9 + ty]        = s2c;
    sred[(tx + 96) * 9 + ty]        = s3;
    sred[1152 + (tx)      * 9 + ty] = q0;
    sred[1152 + (tx + 32) * 9 + ty] = q1;
    sred[1152 + (tx + 64) * 9 + ty] = q2;
    sred[1152 + (tx + 96) * 9 + ty] = q3;
    __syncthreads();
    {
        int stat = tid >> 7, c = tid & 127;
        const float* p = sred + stat * 1152 + c * 9;
        float s = p[0] + p[1] + p[2] + p[3] + p[4] + p[5] + p[6] + p[7];
        g_part[blockIdx.x * 256 + stat * 128 + c] = s;
    }
}

__global__ void bn_finalize_kernel(const float* __restrict__ gamma,
                                   const float* __restrict__ beta) {
    __shared__ float sh_s[512], sh_s2[512];
    int t = threadIdx.x;                 // 512 threads
    int c = t & 127, q = t >> 7;
    float s = 0.f, s2 = 0.f;
    for (int b = q; b < GB_GEMM; b += 4) {
        s += g_part[b * 256 + c];
        s2 += g_part[b * 256 + 128 + c];
    }
    sh_s[t] = s; sh_s2[t] = s2;
    __syncthreads();
    if (q == 0) {
        s = sh_s[c] + sh_s[c + 128] + sh_s[c + 256] + sh_s[c + 384];
        s2 = sh_s2[c] + sh_s2[c + 128] + sh_s2[c + 256] + sh_s2[c + 384];
        const float invM = 1.0f / (float)NN;
        float mu = s * invM;
        float var = s2 * invM - mu * mu;
        float sc = gamma[c] * rsqrtf(var + 1e-5f);
        g_scale[c] = sc;
        g_shift[c] = beta[c] - mu * sc;
    }
}

// ---------------- BN apply + relu (+ residual); h, x0 stored fp16 ----------------
__global__ void bn_apply_kernel(int addRes) {
    int i = blockIdx.x * blockDim.x + threadIdx.x;   // NN*32 items of 4 cols
    int c4 = i & 31;
    float4 v = ((const float4*)g_tmp)[i];
    float4 sc = ((const float4*)g_scale)[c4];
    float4 shv = ((const float4*)g_shift)[c4];
    v.x = fmaxf(v.x * sc.x + shv.x, 0.f);
    v.y = fmaxf(v.y * sc.y + shv.y, 0.f);
    v.z = fmaxf(v.z * sc.z + shv.z, 0.f);
    v.w = fmaxf(v.w * sc.w + shv.w, 0.f);
    if (addRes) {
        uint2 x0p = ((const uint2*)g_x0)[i];
        float2 x01 = __half22float2(*(const __half2*)&x0p.x);
        float2 x23 = __half22float2(*(const __half2*)&x0p.y);
        v.x += x01.x; v.y += x01.y; v.z += x23.x; v.w += x23.y;
    }
    __half2 lo = __floats2half2_rn(v.x, v.y);
    __half2 hi = __floats2half2_rn(v.z, v.w);
    uint2 pack;
    pack.x = *(const unsigned*)&lo;
    pack.y = *(const unsigned*)&hi;
    if (!addRes) ((uint2*)g_x0)[i] = pack;           // first layer: capture residual
    ((uint2*)g_h)[i] = pack;
}

// ---------------- classifier: out = h @ cls_w^T + cls_b, [NN,40] ----------------
__global__ void __launch_bounds__(256) gemm_cls_kernel(const float* __restrict__ W,
                                                       const float* __restrict__ bias,
                                                       float* __restrict__ out) {
    extern __shared__ float sh[];
    float* xs = sh;               // 64*132 (padded)
    float* ws = sh + 64 * 132;    // 128*40 (transposed: ws[k*40+c])
    int tid = threadIdx.x;
    int rowBase = blockIdx.x * 64;

#pragma unroll
    for (int i = 0; i < 20; i++) {        // 40*128 = 5120 = 20*256
        int idx = i * 256 + tid;
        ws[(idx & 127) * 40 + (idx >> 7)] = W[idx];
    }
#pragma unroll
    for (int i = 0; i < 8; i++) {         // 64 rows * 32 uint2 = 2048
        int idx = i * 256 + tid;
        int r = rowBase + (idx >> 5);
        int u = idx & 31;                 // 4 halves per uint2
        float4 f;
        if (r < NN) {
            uint2 hv = ((const uint2*)g_h)[r * 32 + u];
            float2 f01 = __half22float2(*(const __half2*)&hv.x);
            float2 f23 = __half22float2(*(const __half2*)&hv.y);
            f = make_float4(f01.x, f01.y, f23.x, f23.y);
        } else f = make_float4(0.f, 0.f, 0.f, 0.f);
        float* dst = xs + (idx >> 5) * 132 + u * 4;
        dst[0] = f.x; dst[1] = f.y; dst[2] = f.z; dst[3] = f.w;
    }
    __syncthreads();

    int tx = tid & 7;     // cols tx + 8*c
    int ty = tid >> 3;    // rows ty*2, ty*2+1
    float acc[2][5];
#pragma unroll
    for (int j = 0; j < 2; j++)
#pragma unroll
        for (int c = 0; c < 5; c++) acc[j][c] = 0.f;

    const float* x0p = xs + (ty * 2) * 132;
    const float* x1p = x0p + 132;
#pragma unroll 4
    for (int k = 0; k < 128; k++) {
        float xv0 = x0p[k], xv1 = x1p[k];
        const float* wr = ws + k * 40 + tx;
#pragma unroll
        for (int c = 0; c < 5; c++) {
            float wv = wr[8 * c];
            acc[0][c] += xv0 * wv;
            acc[1][c] += xv1 * wv;
        }
    }
#pragma unroll
    for (int j = 0; j < 2; j++) {
        int r = rowBase + ty * 2 + j;
        if (r < NN) {
#pragma unroll
            for (int c = 0; c < 5; c++) {
                int colI = tx + 8 * c;
                out[r * 40 + colI] = acc[j][c] + __ldg(bias + colI);
            }
        }
    }
}

// ---------------- launch ----------------
extern "C" void kernel_launch(void* const* d_in, const int* in_sizes, int n_in,
                              void* d_out, int out_size) {
    const float* x     = (const float*)d_in[0];
    const int*   ei    = (const int*)d_in[1];
    const float* fc_w  = (const float*)d_in[2];
    const float* fc_b  = (const float*)d_in[3];
    const float* convw = (const float*)d_in[4];
    const float* convb = (const float*)d_in[5];
    const float* gamma = (const float*)d_in[6];
    const float* beta  = (const float*)d_in[7];
    const float* clsw  = (const float*)d_in[8];
    const float* clsb  = (const float*)d_in[9];
    float* out = (float*)d_out;
    const int* row = ei;        // edge_index[0]
    const int* col = ei + EE;   // edge_index[1]

    const int smem_gemm = (64 * 128 + 128 * 64 * 2) * 4;  // 98304 B
    const int smem_cls  = (64 * 132 + 128 * 40) * 4;      // 54272 B
    cudaFuncSetAttribute(gemm128_kernel, cudaFuncAttributeMaxDynamicSharedMemorySize, smem_gemm);
    cudaFuncSetAttribute(gemm_cls_kernel, cudaFuncAttributeMaxDynamicSharedMemorySize, smem_cls);

    // ---- CSR build (counting sort by col) + normalization weights ----
    zero_cnt_kernel<<<(NN + 1023) / 1024, 1024>>>();
    compute_cnt_kernel<<<EE / 256, 256>>>(col);
    dinv_kernel<<<(NN + 255) / 256, 256>>>();
    scan1_kernel<<<SCAN_NB, 1024>>>();
    scan2_kernel<<<1, 128>>>();
    scan3_kernel<<<(NN + 255) / 256, 256>>>();
    scatter_kernel<<<EE / 256, 256>>>(row, col);

    const int eltB = NN * 32 / 256;         // 12500

    // input projection + BN + relu, capture x0
    gemm128_kernel<<<GB_GEMM, 256, smem_gemm>>>(x, 0, fc_w, fc_b);
    bn_finalize_kernel<<<1, 512>>>(gamma, beta);
    bn_apply_kernel<<<eltB, 256>>>(0);

    for (int l = 0; l < 3; l++) {
        spmm_csr_kernel<<<NN / 8, 256>>>();
        gemm128_kernel<<<GB_GEMM, 256, smem_gemm>>>(nullptr, 1, convw + l * DD * DD, convb + l * DD);
        bn_finalize_kernel<<<1, 512>>>(gamma + (l + 1) * DD, beta + (l + 1) * DD);
        bn_apply_kernel<<<eltB, 256>>>(1);
    }

    gemm_cls_kernel<<<GB_GEMM, 256, smem_cls>>>(clsw, clsb, out);
}

// round 16
// speedup vs baseline: 1.3782x; 1.3782x over previous
#include <cuda_runtime.h>
#include <cuda_fp16.h>

#define NN 100000
#define EE 1600000
#define DD 128
#define GB_GEMM 1563      // ceil(NN/64) gemm blocks (also BN-stat partials)
#define SCAN_NB 98        // ceil(NN / 1024)

// ---------------- scratch (device globals: no allocation allowed) ----------------
__device__ __align__(16) float g_deg[NN];            // dinv (float)
__device__ __align__(16) int   g_cnt[NN];            // int degree
__device__ __align__(16) int   g_offp[NN];           // per-block exclusive scan
__device__ __align__(16) int   g_off[NN + 1];        // CSR offsets
__device__ __align__(16) int   g_cur[NN];            // scatter cursors
__device__ __align__(16) int   g_bsum[128];          // scan block sums
__device__ __align__(16) int   g_bpre[128];          // scan block prefixes
__device__ __align__(16) int2  g_edge[EE];           // CSR: {row*32, val bits}
__device__ __align__(16) __half g_h[NN * DD];        // current activations (fp16)
__device__ __align__(16) __half g_x0[NN * DD];       // first embedding (fp16)
__device__ __align__(16) float g_tmp[NN * DD];       // GEMM output (pre-BN)
__device__ __align__(16) float g_agg[NN * DD];       // SPMM output (fp32)
__device__ __align__(16) float g_part[GB_GEMM * 256]; // per gemm-block [sum(128)|sumsq(128)]
__device__ __align__(16) float g_scale[DD];
__device__ __align__(16) float g_shift[DD];

// ---------------- degree ----------------
__global__ void zero_cnt_kernel() {
    int i = blockIdx.x * blockDim.x + threadIdx.x;
    if (i < NN) g_cnt[i] = 0;
}

__global__ void compute_cnt_kernel(const int* __restrict__ col) {
    int e = blockIdx.x * blockDim.x + threadIdx.x;   // EE % 256 == 0
    atomicAdd(&g_cnt[col[e]], 1);
}

__global__ void dinv_kernel() {
    int i = blockIdx.x * blockDim.x + threadIdx.x;
    if (i < NN) {
        int d = g_cnt[i];
        g_deg[i] = d > 0 ? rsqrtf((float)d) : 0.f;
    }
}

// ---------------- prefix scan (3 phases) ----------------
__global__ void __launch_bounds__(1024) scan1_kernel() {
    __shared__ int sh[1024];
    int i = blockIdx.x * 1024 + threadIdx.x;
    int v = (i < NN) ? g_cnt[i] : 0;
    sh[threadIdx.x] = v;
    __syncthreads();
#pragma unroll
    for (int off = 1; off < 1024; off <<= 1) {
        int t = 0;
        if (threadIdx.x >= off) t = sh[threadIdx.x - off];
        __syncthreads();
        sh[threadIdx.x] += t;
        __syncthreads();
    }
    if (i < NN) g_offp[i] = sh[threadIdx.x] - v;     // exclusive within block
    if (threadIdx.x == 1023) g_bsum[blockIdx.x] = sh[1023];
}

__global__ void scan2_kernel() {                     // 1 block, 128 threads
    __shared__ int sh[128];
    int t = threadIdx.x;
    int v = (t < SCAN_NB) ? g_bsum[t] : 0;
    sh[t] = v;
    __syncthreads();
#pragma unroll
    for (int off = 1; off < 128; off <<= 1) {
        int u = 0;
        if (t >= off) u = sh[t - off];
        __syncthreads();
        sh[t] += u;
        __syncthreads();
    }
    if (t < SCAN_NB) g_bpre[t] = sh[t] - v;          // exclusive
}

__global__ void scan3_kernel() {
    int i = blockIdx.x * blockDim.x + threadIdx.x;
    if (i < NN) {
        g_off[i] = g_offp[i] + g_bpre[i >> 10];
        g_cur[i] = 0;
    }
    if (i == 0) g_off[NN] = EE;
}

// ---------------- CSR scatter (sort edges by col) + weight ----------------
__global__ void scatter_kernel(const int* __restrict__ row, const int* __restrict__ col) {
    int e = blockIdx.x * blockDim.x + threadIdx.x;   // EE % 256 == 0
    int r = row[e];
    int c = col[e];
    int p = g_off[c] + atomicAdd(&g_cur[c], 1);
    int2 ev;
    ev.x = r * 32;                                   // pre-scaled uint2 row base
    ev.y = __float_as_int(g_deg[c] * g_deg[r]);
    g_edge[p] = ev;
}

// ---------------- SPMM (gather, no atomics): one warp per destination node ----------------
__global__ void __launch_bounds__(256) spmm_csr_kernel() {
    int n = blockIdx.x * 8 + (threadIdx.x >> 5);     // NN % 8 == 0
    int lane = threadIdx.x & 31;
    int s = g_off[n];
    int e = g_off[n + 1];
    float4 acc = make_float4(0.f, 0.f, 0.f, 0.f);
#pragma unroll 4
    for (int p = s; p < e; p++) {
        int2 ev = __ldg(g_edge + p);                 // warp-uniform broadcast
        float v = __int_as_float(ev.y);
        uint2 hv = ((const uint2*)g_h)[ev.x + lane]; // 4 halves (8 B) gather
        float2 f01 = __half22float2(*(const __half2*)&hv.x);
        float2 f23 = __half22float2(*(const __half2*)&hv.y);
        acc.x += v * f01.x; acc.y += v * f01.y;
        acc.z += v * f23.x; acc.w += v * f23.y;
    }
    ((float4*)g_agg)[n * 32 + lane] = acc;
}

// ---------------- 128-wide SGEMM + fused BN stats ----------------
// g_tmp = A @ W^T + bias ; g_part[blk] = per-column {sum, sumsq} of this tile.
// Scalar FFMA inner loop (R8 form — measured at the fp32 FFMA roofline).
__global__ void __launch_bounds__(256) gemm128_kernel(const float* __restrict__ Aext,
                                                      int useAgg,
                                                      const float* __restrict__ W,
                                                      const float* __restrict__ bias) {
    extern __shared__ float sh[];
    float* xs = sh;               // 64*128
    float* ws = sh + 64 * 128;    // 128*129 (transposed, padded: ws[k*129+n])
    const float* A = useAgg ? g_agg : Aext;
    int tid = threadIdx.x;
    int rowBase = blockIdx.x * 64;

#pragma unroll
    for (int i = 0; i < 64; i++) {        // stage W transposed (conflict-free: stride 129)
        int idx = i * 256 + tid;
        ws[(idx & 127) * 129 + (idx >> 7)] = W[idx];
    }
#pragma unroll
    for (int i = 0; i < 32; i++) {        // stage A tile
        int idx = i * 256 + tid;
        int r = rowBase + (idx >> 7);
        xs[idx] = (r < NN) ? A[r * DD + (idx & 127)] : 0.f;
    }
    __syncthreads();

    int tx = tid & 31;        // cols tx, tx+32, tx+64, tx+96
    int ty = tid >> 5;        // rows ty*8 .. ty*8+7
    float acc[8][4];
#pragma unroll
    for (int j = 0; j < 8; j++) { acc[j][0] = acc[j][1] = acc[j][2] = acc[j][3] = 0.f; }

    const float4* xs4 = (const float4*)xs + ty * 8 * 32;
    for (int k4 = 0; k4 < 32; k4++) {
        float w[4][4];
#pragma unroll
        for (int kk = 0; kk < 4; kk++) {
            const float* wr = ws + (k4 * 4 + kk) * 129 + tx;
            w[kk][0] = wr[0]; w[kk][1] = wr[32]; w[kk][2] = wr[64]; w[kk][3] = wr[96];
        }
#pragma unroll
        for (int j = 0; j < 8; j++) {
            float4 xv = xs4[j * 32 + k4];
            acc[j][0] += xv.x * w[0][0]; acc[j][1] += xv.x * w[0][1];
            acc[j][2] += xv.x * w[0][2]; acc[j][3] += xv.x * w[0][3];
            acc[j][0] += xv.y * w[1][0]; acc[j][1] += xv.y * w[1][1];
            acc[j][2] += xv.y * w[1][2]; acc[j][3] += xv.y * w[1][3];
            acc[j][0] += xv.z * w[2][0]; acc[j][1] += xv.z * w[2][1];
            acc[j][2] += xv.z * w[2][2]; acc[j][3] += xv.z * w[2][3];
            acc[j][0] += xv.w * w[3][0]; acc[j][1] += xv.w * w[3][1];
            acc[j][2] += xv.w * w[3][2]; acc[j][3] += xv.w * w[3][3];
        }
    }

    float b0 = __ldg(bias + tx), b1 = __ldg(bias + tx + 32);
    float b2 = __ldg(bias + tx + 64), b3 = __ldg(bias + tx + 96);
    float s0 = 0.f, s1 = 0.f, s2c = 0.f, s3 = 0.f;       // col sums
    float q0 = 0.f, q1 = 0.f, q2 = 0.f, q3 = 0.f;        // col sumsq
#pragma unroll
    for (int j = 0; j < 8; j++) {
        int r = rowBase + ty * 8 + j;
        if (r < NN) {
            float v0 = acc[j][0] + b0;
            float v1 = acc[j][1] + b1;
            float v2 = acc[j][2] + b2;
            float v3 = acc[j][3] + b3;
            float* o = g_tmp + r * DD + tx;
            o[0] = v0; o[32] = v1; o[64] = v2; o[96] = v3;
            s0 += v0; s1 += v1; s2c += v2; s3 += v3;
            q0 += v0 * v0; q1 += v1 * v1; q2 += v2 * v2; q3 += v3 * v3;
        }
    }

    // reduce stats over the 8 row-groups (reuse xs; padded stride 9)
    __syncthreads();
    float* sred = sh;     // [stat][c][ty] : stat*1152 + c*9 + ty
    sred[(tx)      * 9 + ty]        = s0;
    sred[(tx + 32) * 9 + ty]        = s1;
    sred[(tx + 64) * 9 + ty]        = s2c;
    sred[(tx + 96) * 9 + ty]        = s3;
    sred[1152 + (tx)      * 9 + ty] = q0;
    sred[1152 + (tx + 32) * 9 + ty] = q1;
    sred[1152 + (tx + 64) * 9 + ty] = q2;
    sred[1152 + (tx + 96) * 9 + ty] = q3;
    __syncthreads();
    {
        int stat = tid >> 7, c = tid & 127;
        const float* p = sred + stat * 1152 + c * 9;
        float s = p[0] + p[1] + p[2] + p[3] + p[4] + p[5] + p[6] + p[7];
        g_part[blockIdx.x * 256 + stat * 128 + c] = s;
    }
}

__global__ void bn_finalize_kernel(const float* __restrict__ gamma,
                                   const float* __restrict__ beta) {
    __shared__ float sh_s[512], sh_s2[512];
    int t = threadIdx.x;                 // 512 threads
    int c = t & 127, q = t >> 7;
    float s = 0.f, s2 = 0.f;
    for (int b = q; b < GB_GEMM; b += 4) {
        s += g_part[b * 256 + c];
        s2 += g_part[b * 256 + 128 + c];
    }
    sh_s[t] = s; sh_s2[t] = s2;
    __syncthreads();
    if (q == 0) {
        s = sh_s[c] + sh_s[c + 128] + sh_s[c + 256] + sh_s[c + 384];
        s2 = sh_s2[c] + sh_s2[c + 128] + sh_s2[c + 256] + sh_s2[c + 384];
        const float invM = 1.0f / (float)NN;
        float mu = s * invM;
        float var = s2 * invM - mu * mu;
        float sc = gamma[c] * rsqrtf(var + 1e-5f);
        g_scale[c] = sc;
        g_shift[c] = beta[c] - mu * sc;
    }
}

// ---------------- BN apply + relu (+ residual); h, x0 stored fp16 ----------------
__global__ void bn_apply_kernel(int addRes) {
    int i = blockIdx.x * blockDim.x + threadIdx.x;   // NN*32 items of 4 cols
    int c4 = i & 31;
    float4 v = ((const float4*)g_tmp)[i];
    float4 sc = ((const float4*)g_scale)[c4];
    float4 shv = ((const float4*)g_shift)[c4];
    v.x = fmaxf(v.x * sc.x + shv.x, 0.f);
    v.y = fmaxf(v.y * sc.y + shv.y, 0.f);
    v.z = fmaxf(v.z * sc.z + shv.z, 0.f);
    v.w = fmaxf(v.w * sc.w + shv.w, 0.f);
    if (addRes) {
        uint2 x0p = ((const uint2*)g_x0)[i];
        float2 x01 = __half22float2(*(const __half2*)&x0p.x);
        float2 x23 = __half22float2(*(const __half2*)&x0p.y);
        v.x += x01.x; v.y += x01.y; v.z += x23.x; v.w += x23.y;
    }
    __half2 lo = __floats2half2_rn(v.x, v.y);
    __half2 hi = __floats2half2_rn(v.z, v.w);
    uint2 pack;
    pack.x = *(const unsigned*)&lo;
    pack.y = *(const unsigned*)&hi;
    if (!addRes) ((uint2*)g_x0)[i] = pack;           // first layer: capture residual
    ((uint2*)g_h)[i] = pack;
}

// ---------------- classifier: out = h @ cls_w^T + cls_b, [NN,40] ----------------
__global__ void __launch_bounds__(256) gemm_cls_kernel(const float* __restrict__ W,
                                                       const float* __restrict__ bias,
                                                       float* __restrict__ out) {
    extern __shared__ float sh[];
    float* xs = sh;               // 64*132 (padded)
    float* ws = sh + 64 * 132;    // 128*40 (transposed: ws[k*40+c])
    int tid = threadIdx.x;
    int rowBase = blockIdx.x * 64;

#pragma unroll
    for (int i = 0; i < 20; i++) {        // 40*128 = 5120 = 20*256
        int idx = i * 256 + tid;
        ws[(idx & 127) * 40 + (idx >> 7)] = W[idx];
    }
#pragma unroll
    for (int i = 0; i < 8; i++) {         // 64 rows * 32 uint2 = 2048
        int idx = i * 256 + tid;
        int r = rowBase + (idx >> 5);
        int u = idx & 31;                 // 4 halves per uint2
        float4 f;
        if (r < NN) {
            uint2 hv = ((const uint2*)g_h)[r * 32 + u];
            float2 f01 = __half22float2(*(const __half2*)&hv.x);
            float2 f23 = __half22float2(*(const __half2*)&hv.y);
            f = make_float4(f01.x, f01.y, f23.x, f23.y);
        } else f = make_float4(0.f, 0.f, 0.f, 0.f);
        float* dst = xs + (idx >> 5) * 132 + u * 4;
        dst[0] = f.x; dst[1] = f.y; dst[2] = f.z; dst[3] = f.w;
    }
    __syncthreads();

    int tx = tid & 7;     // cols tx + 8*c
    int ty = tid >> 3;    // rows ty*2, ty*2+1
    float acc[2][5];
#pragma unroll
    for (int j = 0; j < 2; j++)
#pragma unroll
        for (int c = 0; c < 5; c++) acc[j][c] = 0.f;

    const float* x0p = xs + (ty * 2) * 132;
    const float* x1p = x0p + 132;
#pragma unroll 4
    for (int k = 0; k < 128; k++) {
        float xv0 = x0p[k], xv1 = x1p[k];
        const float* wr = ws + k * 40 + tx;
#pragma unroll
        for (int c = 0; c < 5; c++) {
            float wv = wr[8 * c];
            acc[0][c] += xv0 * wv;
            acc[1][c] += xv1 * wv;
        }
    }
#pragma unroll
    for (int j = 0; j < 2; j++) {
        int r = rowBase + ty * 2 + j;
        if (r < NN) {
#pragma unroll
            for (int c = 0; c < 5; c++) {
                int colI = tx + 8 * c;
                out[r * 40 + colI] = acc[j][c] + __ldg(bias + colI);
            }
        }
    }
}

// ---------------- launch ----------------
extern "C" void kernel_launch(void* const* d_in, const int* in_sizes, int n_in,
                              void* d_out, int out_size) {
    const float* x     = (const float*)d_in[0];
    const int*   ei    = (const int*)d_in[1];
    const float* fc_w  = (const float*)d_in[2];
    const float* fc_b  = (const float*)d_in[3];
    const float* convw = (const float*)d_in[4];
    const float* convb = (const float*)d_in[5];
    const float* gamma = (const float*)d_in[6];
    const float* beta  = (const float*)d_in[7];
    const float* clsw  = (const float*)d_in[8];
    const float* clsb  = (const float*)d_in[9];
    float* out = (float*)d_out;
    const int* row = ei;        // edge_index[0]
    const int* col = ei + EE;   // edge_index[1]

    const int smem_gemm = (64 * 128 + 128 * 129) * 4;   // 98816 B
    const int smem_cls  = (64 * 132 + 128 * 40) * 4;    // 54272 B
    cudaFuncSetAttribute(gemm128_kernel, cudaFuncAttributeMaxDynamicSharedMemorySize, smem_gemm);
    cudaFuncSetAttribute(gemm_cls_kernel, cudaFuncAttributeMaxDynamicSharedMemorySize, smem_cls);

    // ---- CSR build (counting sort by col) + normalization weights ----
    zero_cnt_kernel<<<(NN + 1023) / 1024, 1024>>>();
    compute_cnt_kernel<<<EE / 256, 256>>>(col);
    dinv_kernel<<<(NN + 255) / 256, 256>>>();
    scan1_kernel<<<SCAN_NB, 1024>>>();
    scan2_kernel<<<1, 128>>>();
    scan3_kernel<<<(NN + 255) / 256, 256>>>();
    scatter_kernel<<<EE / 256, 256>>>(row, col);

    const int eltB = NN * 32 / 256;         // 12500

    // input projection + BN + relu, capture x0
    gemm128_kernel<<<GB_GEMM, 256, smem_gemm>>>(x, 0, fc_w, fc_b);
    bn_finalize_kernel<<<1, 512>>>(gamma, beta);
    bn_apply_kernel<<<eltB, 256>>>(0);

    for (int l = 0; l < 3; l++) {
        spmm_csr_kernel<<<NN / 8, 256>>>();
        gemm128_kernel<<<GB_GEMM, 256, smem_gemm>>>(nullptr, 1, convw + l * DD * DD, convb + l * DD);
        bn_finalize_kernel<<<1, 512>>>(gamma + (l + 1) * DD, beta + (l + 1) * DD);
        bn_apply_kernel<<<eltB, 256>>>(1);
    }

    gemm_cls_kernel<<<GB_GEMM, 256, smem_cls>>>(clsw, clsb, out);
}

// round 17
// speedup vs baseline: 1.7406x; 1.2629x over previous
#include <cuda_runtime.h>
#include <cuda_fp16.h>

#define NN 100000
#define EE 1600000
#define DD 128
#define STAT_BLOCKS 1000  // NN / 100 rows per block
#define SCAN_NB 98        // ceil(NN / 1024)

// ---------------- scratch (device globals: no allocation allowed) ----------------
__device__ __align__(16) float g_deg[NN];            // dinv (float)
__device__ __align__(16) int   g_cnt[NN];            // int degree
__device__ __align__(16) int   g_offp[NN];           // per-block exclusive scan
__device__ __align__(16) int   g_off[NN + 1];        // CSR offsets
__device__ __align__(16) int   g_cur[NN];            // scatter cursors
__device__ __align__(16) int   g_bsum[128];          // scan block sums
__device__ __align__(16) int   g_bpre[128];          // scan block prefixes
__device__ __align__(16) int2  g_edge[EE];           // CSR: {row*32, val bits}
__device__ __align__(16) __half g_h[NN * DD];        // current activations (fp16)
__device__ __align__(16) __half g_x0[NN * DD];       // first embedding (fp16)
__device__ __align__(16) float g_tmp[NN * DD];       // GEMM output (pre-BN)
__device__ __align__(16) float g_agg[NN * DD];       // SPMM output (fp32)
__device__ __align__(16) float g_part[STAT_BLOCKS * 256]; // [sum(128)|sumsq(128)]
__device__ __align__(16) float g_scale[DD];
__device__ __align__(16) float g_shift[DD];

// mma.sync m16n8k16 fp16 inputs, fp32 accum (fallback HMMA on sm_103a)
#define MMA16816(d, a0, a1, a2, a3, b0, b1)                              \
    asm volatile(                                                        \
        "mma.sync.aligned.m16n8k16.row.col.f32.f16.f16.f32 "             \
        "{%0,%1,%2,%3}, {%4,%5,%6,%7}, {%8,%9}, {%0,%1,%2,%3};"          \
        : "+f"((d)[0]), "+f"((d)[1]), "+f"((d)[2]), "+f"((d)[3])         \
        : "r"(a0), "r"(a1), "r"(a2), "r"(a3), "r"(b0), "r"(b1))

// ---------------- degree ----------------
__global__ void zero_cnt_kernel() {
    int i = blockIdx.x * blockDim.x + threadIdx.x;
    if (i < NN) g_cnt[i] = 0;
}

__global__ void compute_cnt_kernel(const int* __restrict__ col) {
    int e = blockIdx.x * blockDim.x + threadIdx.x;   // EE % 256 == 0
    atomicAdd(&g_cnt[col[e]], 1);
}

__global__ void dinv_kernel() {
    int i = blockIdx.x * blockDim.x + threadIdx.x;
    if (i < NN) {
        int d = g_cnt[i];
        g_deg[i] = d > 0 ? rsqrtf((float)d) : 0.f;
    }
}

// ---------------- prefix scan (3 phases) ----------------
__global__ void __launch_bounds__(1024) scan1_kernel() {
    __shared__ int sh[1024];
    int i = blockIdx.x * 1024 + threadIdx.x;
    int v = (i < NN) ? g_cnt[i] : 0;
    sh[threadIdx.x] = v;
    __syncthreads();
#pragma unroll
    for (int off = 1; off < 1024; off <<= 1) {
        int t = 0;
        if (threadIdx.x >= off) t = sh[threadIdx.x - off];
        __syncthreads();
        sh[threadIdx.x] += t;
        __syncthreads();
    }
    if (i < NN) g_offp[i] = sh[threadIdx.x] - v;     // exclusive within block
    if (threadIdx.x == 1023) g_bsum[blockIdx.x] = sh[1023];
}

__global__ void scan2_kernel() {                     // 1 block, 128 threads
    __shared__ int sh[128];
    int t = threadIdx.x;
    int v = (t < SCAN_NB) ? g_bsum[t] : 0;
    sh[t] = v;
    __syncthreads();
#pragma unroll
    for (int off = 1; off < 128; off <<= 1) {
        int u = 0;
        if (t >= off) u = sh[t - off];
        __syncthreads();
        sh[t] += u;
        __syncthreads();
    }
    if (t < SCAN_NB) g_bpre[t] = sh[t] - v;          // exclusive
}

__global__ void scan3_kernel() {
    int i = blockIdx.x * blockDim.x + threadIdx.x;
    if (i < NN) {
        g_off[i] = g_offp[i] + g_bpre[i >> 10];
        g_cur[i] = 0;
    }
    if (i == 0) g_off[NN] = EE;
}

// ---------------- CSR scatter (sort edges by col) + weight ----------------
__global__ void scatter_kernel(const int* __restrict__ row, const int* __restrict__ col) {
    int e = blockIdx.x * blockDim.x + threadIdx.x;   // EE % 256 == 0
    int r = row[e];
    int c = col[e];
    int p = g_off[c] + atomicAdd(&g_cur[c], 1);
    int2 ev;
    ev.x = r * 32;                                   // pre-scaled uint2 row base
    ev.y = __float_as_int(g_deg[c] * g_deg[r]);
    g_edge[p] = ev;
}

// ---------------- SPMM (gather, no atomics): one warp per destination node ----------------
__global__ void __launch_bounds__(256) spmm_csr_kernel() {
    int n = blockIdx.x * 8 + (threadIdx.x >> 5);     // NN % 8 == 0
    int lane = threadIdx.x & 31;
    int s = g_off[n];
    int e = g_off[n + 1];
    float4 acc = make_float4(0.f, 0.f, 0.f, 0.f);
#pragma unroll 4
    for (int p = s; p < e; p++) {
        int2 ev = __ldg(g_edge + p);                 // warp-uniform broadcast
        float v = __int_as_float(ev.y);
        uint2 hv = ((const uint2*)g_h)[ev.x + lane]; // 4 halves (8 B) gather
        float2 f01 = __half22float2(*(const __half2*)&hv.x);
        float2 f23 = __half22float2(*(const __half2*)&hv.y);
        acc.x += v * f01.x; acc.y += v * f01.y;
        acc.z += v * f23.x; acc.w += v * f23.y;
    }
    ((float4*)g_agg)[n * 32 + lane] = acc;
}

// ---------------- 128-wide GEMM via split-fp16 HMMA (exact to ~2^-22) ----------------
// g_tmp = A @ W^T + bias.  A,W split into hi+lo fp16; D = Ah*Wh + Ah*Wl + Al*Wh (fp32 acc).
// Block: 256 thr (8 warps), tile 64 rows x 128 cols, K=128.
// Warp (rg = wid>>1, cg = wid&1) computes rows [rg*16,+16), cols [cg*64,+64) = 8 n8-tiles.
// Shared rows padded to 136 halves (68 words; 68%32=4 -> conflict-free fragment loads).
__global__ void __launch_bounds__(256) gemm128_tc_kernel(const float* __restrict__ Aext,
                                                         int useAgg,
                                                         const float* __restrict__ W,
                                                         const float* __restrict__ bias) {
    extern __shared__ __half shh[];
    __half* xs_hi = shh;                  // 64*136
    __half* xs_lo = shh + 64 * 136;       // 64*136
    __half* ws_hi = shh + 128 * 136;      // 128*136
    __half* ws_lo = shh + 256 * 136;      // 128*136
    const float* A = useAgg ? g_agg : Aext;
    int tid = threadIdx.x;
    int rowBase = blockIdx.x * 64;

    // stage W split: 8192 float2
    const float2* W2 = (const float2*)W;
#pragma unroll
    for (int i = 0; i < 32; i++) {
        int idx = i * 256 + tid;
        int n = idx >> 6, kp = idx & 63;
        float2 w = W2[idx];
        __half hx = __float2half_rn(w.x), hy = __float2half_rn(w.y);
        __half lx = __float2half_rn(w.x - __half2float(hx));
        __half ly = __float2half_rn(w.y - __half2float(hy));
        ((__half2*)ws_hi)[n * 68 + kp] = __halves2half2(hx, hy);
        ((__half2*)ws_lo)[n * 68 + kp] = __halves2half2(lx, ly);
    }
    // stage A split: 4096 float2
#pragma unroll
    for (int i = 0; i < 16; i++) {
        int idx = i * 256 + tid;
        int m = idx >> 6, kp = idx & 63;
        int r = rowBase + m;
        float2 a = (r < NN) ? ((const float2*)A)[r * 64 + kp] : make_float2(0.f, 0.f);
        __half hx = __float2half_rn(a.x), hy = __float2half_rn(a.y);
        __half lx = __float2half_rn(a.x - __half2float(hx));
        __half ly = __float2half_rn(a.y - __half2float(hy));
        ((__half2*)xs_hi)[m * 68 + kp] = __halves2half2(hx, hy);
        ((__half2*)xs_lo)[m * 68 + kp] = __halves2half2(lx, ly);
    }
    __syncthreads();

    int wid = tid >> 5, lane = tid & 31;
    int rg = wid >> 1, cg = wid & 1;
    int qm = lane >> 2, qk = lane & 3;               // fragment row / k-pair
    float acc[8][4];
#pragma unroll
    for (int j = 0; j < 8; j++) { acc[j][0] = acc[j][1] = acc[j][2] = acc[j][3] = 0.f; }

    const __half* axh = xs_hi + (rg * 16 + qm) * 136 + qk * 2;
    const __half* axl = xs_lo + (rg * 16 + qm) * 136 + qk * 2;
#pragma unroll
    for (int ks = 0; ks < 8; ks++) {
        int k0 = ks * 16;
        unsigned ah0 = *(const unsigned*)(axh + k0);
        unsigned ah1 = *(const unsigned*)(axh + 8 * 136 + k0);
        unsigned ah2 = *(const unsigned*)(axh + k0 + 8);
        unsigned ah3 = *(const unsigned*)(axh + 8 * 136 + k0 + 8);
        unsigned al0 = *(const unsigned*)(axl + k0);
        unsigned al1 = *(const unsigned*)(axl + 8 * 136 + k0);
        unsigned al2 = *(const unsigned*)(axl + k0 + 8);
        unsigned al3 = *(const unsigned*)(axl + 8 * 136 + k0 + 8);
#pragma unroll
        for (int j = 0; j < 8; j++) {
            int n = cg * 64 + j * 8 + qm;
            const __half* bh = ws_hi + n * 136 + qk * 2;
            const __half* bl = ws_lo + n * 136 + qk * 2;
            unsigned bh0 = *(const unsigned*)(bh + k0);
            unsigned bh1 = *(const unsigned*)(bh + k0 + 8);
            unsigned bl0 = *(const unsigned*)(bl + k0);
            unsigned bl1 = *(const unsigned*)(bl + k0 + 8);
            MMA16816(acc[j], ah0, ah1, ah2, ah3, bh0, bh1);
            MMA16816(acc[j], ah0, ah1, ah2, ah3, bl0, bl1);
            MMA16816(acc[j], al0, al1, al2, al3, bh0, bh1);
        }
    }

    // epilogue: c0,c1 -> row qm; c2,c3 -> row qm+8; cols j*8 + qk*2 (+1)
    int r0 = rowBase + rg * 16 + qm;
    int r1 = r0 + 8;
#pragma unroll
    for (int j = 0; j < 8; j++) {
        int c0 = cg * 64 + j * 8 + qk * 2;
        float b0 = __ldg(bias + c0), b1 = __ldg(bias + c0 + 1);
        if (r0 < NN) {
            float2 v = make_float2(acc[j][0] + b0, acc[j][1] + b1);
            *(float2*)(g_tmp + r0 * DD + c0) = v;
        }
        if (r1 < NN) {
            float2 v = make_float2(acc[j][2] + b0, acc[j][3] + b1);
            *(float2*)(g_tmp + r1 * DD + c0) = v;
        }
    }
}

// ---------------- BN stats (two-stage, no atomics) ----------------
__global__ void col_stats_kernel() {
    int c = threadIdx.x;                 // 128 threads, one per column
    int r0 = blockIdx.x * 100;           // NN / STAT_BLOCKS
    float s = 0.f, s2 = 0.f;
#pragma unroll 4
    for (int r = r0; r < r0 + 100; r++) {
        float v = g_tmp[r * DD + c];
        s += v; s2 += v * v;
    }
    g_part[blockIdx.x * 256 + c] = s;
    g_part[blockIdx.x * 256 + 128 + c] = s2;
}

__global__ void bn_finalize_kernel(const float* __restrict__ gamma,
                                   const float* __restrict__ beta) {
    __shared__ float sh_s[512], sh_s2[512];
    int t = threadIdx.x;                 // 512 threads
    int c = t & 127, q = t >> 7;
    float s = 0.f, s2 = 0.f;
    for (int b = q; b < STAT_BLOCKS; b += 4) {
        s += g_part[b * 256 + c];
        s2 += g_part[b * 256 + 128 + c];
    }
    sh_s[t] = s; sh_s2[t] = s2;
    __syncthreads();
    if (q == 0) {
        s = sh_s[c] + sh_s[c + 128] + sh_s[c + 256] + sh_s[c + 384];
        s2 = sh_s2[c] + sh_s2[c + 128] + sh_s2[c + 256] + sh_s2[c + 384];
        const float invM = 1.0f / (float)NN;
        float mu = s * invM;
        float var = s2 * invM - mu * mu;
        float sc = gamma[c] * rsqrtf(var + 1e-5f);
        g_scale[c] = sc;
        g_shift[c] = beta[c] - mu * sc;
    }
}

// ---------------- BN apply + relu (+ residual); h, x0 stored fp16 ----------------
__global__ void bn_apply_kernel(int addRes) {
    int i = blockIdx.x * blockDim.x + threadIdx.x;   // NN*32 items of 4 cols
    int c4 = i & 31;
    float4 v = ((const float4*)g_tmp)[i];
    float4 sc = ((const float4*)g_scale)[c4];
    float4 shv = ((const float4*)g_shift)[c4];
    v.x = fmaxf(v.x * sc.x + shv.x, 0.f);
    v.y = fmaxf(v.y * sc.y + shv.y, 0.f);
    v.z = fmaxf(v.z * sc.z + shv.z, 0.f);
    v.w = fmaxf(v.w * sc.w + shv.w, 0.f);
    if (addRes) {
        uint2 x0p = ((const uint2*)g_x0)[i];
        float2 x01 = __half22float2(*(const __half2*)&x0p.x);
        float2 x23 = __half22float2(*(const __half2*)&x0p.y);
        v.x += x01.x; v.y += x01.y; v.z += x23.x; v.w += x23.y;
    }
    __half2 lo = __floats2half2_rn(v.x, v.y);
    __half2 hi = __floats2half2_rn(v.z, v.w);
    uint2 pack;
    pack.x = *(const unsigned*)&lo;
    pack.y = *(const unsigned*)&hi;
    if (!addRes) ((uint2*)g_x0)[i] = pack;           // first layer: capture residual
    ((uint2*)g_h)[i] = pack;
}

// ---------------- classifier: out = h @ cls_w^T + cls_b, [NN,40] ----------------
__global__ void __launch_bounds__(256) gemm_cls_kernel(const float* __restrict__ W,
                                                       const float* __restrict__ bias,
                                                       float* __restrict__ out) {
    extern __shared__ float sh[];
    float* xs = sh;               // 64*132 (padded)
    float* ws = sh + 64 * 132;    // 128*40 (transposed: ws[k*40+c])
    int tid = threadIdx.x;
    int rowBase = blockIdx.x * 64;

#pragma unroll
    for (int i = 0; i < 20; i++) {        // 40*128 = 5120 = 20*256
        int idx = i * 256 + tid;
        ws[(idx & 127) * 40 + (idx >> 7)] = W[idx];
    }
#pragma unroll
    for (int i = 0; i < 8; i++) {         // 64 rows * 32 uint2 = 2048
        int idx = i * 256 + tid;
        int r = rowBase + (idx >> 5);
        int u = idx & 31;                 // 4 halves per uint2
        float4 f;
        if (r < NN) {
            uint2 hv = ((const uint2*)g_h)[r * 32 + u];
            float2 f01 = __half22float2(*(const __half2*)&hv.x);
            float2 f23 = __half22float2(*(const __half2*)&hv.y);
            f = make_float4(f01.x, f01.y, f23.x, f23.y);
        } else f = make_float4(0.f, 0.f, 0.f, 0.f);
        float* dst = xs + (idx >> 5) * 132 + u * 4;
        dst[0] = f.x; dst[1] = f.y; dst[2] = f.z; dst[3] = f.w;
    }
    __syncthreads();

    int tx = tid & 7;     // cols tx + 8*c
    int ty = tid >> 3;    // rows ty*2, ty*2+1
    float acc[2][5];
#pragma unroll
    for (int j = 0; j < 2; j++)
#pragma unroll
        for (int c = 0; c < 5; c++) acc[j][c] = 0.f;

    const float* x0p = xs + (ty * 2) * 132;
    const float* x1p = x0p + 132;
#pragma unroll 4
    for (int k = 0; k < 128; k++) {
        float xv0 = x0p[k], xv1 = x1p[k];
        const float* wr = ws + k * 40 + tx;
#pragma unroll
        for (int c = 0; c < 5; c++) {
            float wv = wr[8 * c];
            acc[0][c] += xv0 * wv;
            acc[1][c] += xv1 * wv;
        }
    }
#pragma unroll
    for (int j = 0; j < 2; j++) {
        int r = rowBase + ty * 2 + j;
        if (r < NN) {
#pragma unroll
            for (int c = 0; c < 5; c++) {
                int colI = tx + 8 * c;
                out[r * 40 + colI] = acc[j][c] + __ldg(bias + colI);
            }
        }
    }
}

// ---------------- launch ----------------
extern "C" void kernel_launch(void* const* d_in, const int* in_sizes, int n_in,
                              void* d_out, int out_size) {
    const float* x     = (const float*)d_in[0];
    const int*   ei    = (const int*)d_in[1];
    const float* fc_w  = (const float*)d_in[2];
    const float* fc_b  = (const float*)d_in[3];
    const float* convw = (const float*)d_in[4];
    const float* convb = (const float*)d_in[5];
    const float* gamma = (const float*)d_in[6];
    const float* beta  = (const float*)d_in[7];
    const float* clsw  = (const float*)d_in[8];
    const float* clsb  = (const float*)d_in[9];
    float* out = (float*)d_out;
    const int* row = ei;        // edge_index[0]
    const int* col = ei + EE;   // edge_index[1]

    const int smem_tc  = 384 * 136 * 2;                 // 104448 B
    const int smem_cls = (64 * 132 + 128 * 40) * 4;     // 54272 B
    cudaFuncSetAttribute(gemm128_tc_kernel, cudaFuncAttributeMaxDynamicSharedMemorySize, smem_tc);
    cudaFuncSetAttribute(gemm_cls_kernel, cudaFuncAttributeMaxDynamicSharedMemorySize, smem_cls);

    // ---- CSR build (counting sort by col) + normalization weights ----
    zero_cnt_kernel<<<(NN + 1023) / 1024, 1024>>>();
    compute_cnt_kernel<<<EE / 256, 256>>>(col);
    dinv_kernel<<<(NN + 255) / 256, 256>>>();
    scan1_kernel<<<SCAN_NB, 1024>>>();
    scan2_kernel<<<1, 128>>>();
    scan3_kernel<<<(NN + 255) / 256, 256>>>();
    scatter_kernel<<<EE / 256, 256>>>(row, col);

    const int gB = (NN + 63) / 64;          // 1563
    const int eltB = NN * 32 / 256;         // 12500

    // input projection + BN + relu, capture x0
    gemm128_tc_kernel<<<gB, 256, smem_tc>>>(x, 0, fc_w, fc_b);
    col_stats_kernel<<<STAT_BLOCKS, 128>>>();
    bn_finalize_kernel<<<1, 512>>>(gamma, beta);
    bn_apply_kernel<<<eltB, 256>>>(0);

    for (int l = 0; l < 3; l++) {
        spmm_csr_kernel<<<NN / 8, 256>>>();
        gemm128_tc_kernel<<<gB, 256, smem_tc>>>(nullptr, 1, convw + l * DD * DD, convb + l * DD);
        col_stats_kernel<<<STAT_BLOCKS, 128>>>();
        bn_finalize_kernel<<<1, 512>>>(gamma + (l + 1) * DD, beta + (l + 1) * DD);
        bn_apply_kernel<<<eltB, 256>>>(1);
    }

    gemm_cls_kernel<<<gB, 256, smem_cls>>>(clsw, clsb, out);
}